// round 9
// baseline (speedup 1.0000x reference)
#include <cuda_runtime.h>
#include <cuda_bf16.h>
#include <cstdint>

#define BB 2
#define HH 16
#define LL 2048
#define DD 64
#define TOPK 64
#define QT 16           // queries per CTA
#define KC 128          // keys per chunk
#define NCHUNK (LL/KC)  // 16
#define NWARP 16
#define NTHREADS 512
#define SCORE_STRIDE 2052   // padded fp32 stride

// ---- smem layout (bytes) ----
#define SC_BYTES   (QT*SCORE_STRIDE*4)        // 131328
#define KBUF_OFF   SC_BYTES
#define KSTAGE     32768                      // khi(16K) + klo(16K) per stage
#define QHI_OFF    (KBUF_OFF + 2*KSTAGE)      // +65536
#define QLO_OFF    (QHI_OFF + QT*128)         // +2048
#define HIST_OFF   (QLO_OFF + QT*128)         // +2048
#define SIDX_OFF   (HIST_OFF + NWARP*256*4)   // +16384
#define EIDX_OFF   (SIDX_OFF + NWARP*64*4)    // +4096
#define SMEM_BYTES (EIDX_OFF + NWARP*64*4)    // 225536 total

// ---- persistent bf16 hi/lo split of K (prep kernel output) ----
#define PREP_N (BB*HH*LL*DD/4)   // 1,048,576 float4 groups
__device__ __align__(16) uint2 KhiG[PREP_N];   // 8MB
__device__ __align__(16) uint2 KloG[PREP_N];   // 8MB

__device__ __forceinline__ uint32_t swz(uint32_t o) { return o ^ ((o >> 3) & 0x70u); }
__device__ __forceinline__ uint32_t sptr(const void* p) {
    return (uint32_t)__cvta_generic_to_shared(p);
}
__device__ __forceinline__ uint32_t pack_bf16(float a, float b) {
    __nv_bfloat162 t = __floats2bfloat162_rn(a, b);
    return *reinterpret_cast<uint32_t*>(&t);
}
__device__ __forceinline__ void cp_async16(uint32_t dst, const void* src) {
    asm volatile("cp.async.cg.shared.global [%0], [%1], 16;" :: "r"(dst), "l"(src));
}
__device__ __forceinline__ void ldsm_x4(uint32_t a[4], uint32_t addr) {
    asm volatile("ldmatrix.sync.aligned.m8n8.x4.shared.b16 {%0,%1,%2,%3}, [%4];"
                 : "=r"(a[0]), "=r"(a[1]), "=r"(a[2]), "=r"(a[3]) : "r"(addr));
}
__device__ __forceinline__ void mma16816(float c[4], const uint32_t a[4], const uint32_t b[2]) {
    asm volatile("mma.sync.aligned.m16n8k16.row.col.f32.bf16.bf16.f32 "
                 "{%0,%1,%2,%3}, {%4,%5,%6,%7}, {%8,%9}, {%0,%1,%2,%3};"
                 : "+f"(c[0]), "+f"(c[1]), "+f"(c[2]), "+f"(c[3])
                 : "r"(a[0]), "r"(a[1]), "r"(a[2]), "r"(a[3]), "r"(b[0]), "r"(b[1]));
}
// sign-flip trick: monotonic unsigned ordering of floats
__device__ __forceinline__ unsigned ordkey(float f) {
    unsigned u = __float_as_uint(f);
    return (u & 0x80000000u) ? ~u : (u | 0x80000000u);
}

// ---- prep: split K into bf16 hi + residual-lo, stored bf16-row-major ----
__global__ __launch_bounds__(256) void prep_k_kernel(const float4* __restrict__ K) {
    int i = blockIdx.x * 256 + threadIdx.x;
    float4 v = K[i];
    __nv_bfloat162 h01 = __floats2bfloat162_rn(v.x, v.y);
    __nv_bfloat162 h23 = __floats2bfloat162_rn(v.z, v.w);
    float l0 = v.x - __bfloat162float(h01.x);
    float l1 = v.y - __bfloat162float(h01.y);
    float l2 = v.z - __bfloat162float(h23.x);
    float l3 = v.w - __bfloat162float(h23.y);
    KhiG[i] = make_uint2(*reinterpret_cast<uint32_t*>(&h01),
                         *reinterpret_cast<uint32_t*>(&h23));
    KloG[i] = make_uint2(pack_bf16(l0, l1), pack_bf16(l2, l3));
}

// warp-level scan over a 256-bin histogram: find digit bucket crossing rank r
__device__ __forceinline__ void hist_scan(const uint32_t* myhist, int lane, int r,
                                          int& bsel, int& rnew) {
    const unsigned FULL = 0xFFFFFFFFu;
    unsigned h[8], s = 0;
    int b0 = lane * 8;
#pragma unroll
    for (int j = 0; j < 8; j++) { h[j] = myhist[b0 + j]; s += h[j]; }
    unsigned t = s;                 // suffix-inclusive scan (high lanes = high digits)
#pragma unroll
    for (int d = 1; d < 32; d <<= 1) {
        unsigned v = __shfl_down_sync(FULL, t, d);
        if (lane + d < 32) t += v;
    }
    unsigned above = t - s;
    bool cross = (above < (unsigned)r) && ((unsigned)r <= t);
    unsigned cmask = __ballot_sync(FULL, cross);
    int src = __ffs(cmask) - 1;
    int bs = 0, rn = 0;
    if (cross) {
        unsigned cum = above;
#pragma unroll
        for (int j = 7; j >= 0; j--) {
            cum += h[j];
            if (cum >= (unsigned)r) { bs = b0 + j; rn = r - (int)(cum - h[j]); break; }
        }
    }
    bsel = __shfl_sync(FULL, bs, src);
    rnew = __shfl_sync(FULL, rn, src);
}

__global__ __launch_bounds__(NTHREADS, 1)
void topk_attn_kernel(const float* __restrict__ Qg, const float* __restrict__ Vg,
                      float* __restrict__ Og)
{
    extern __shared__ char smem[];
    float*    sc    = (float*)smem;
    char*     qhi   = smem + QHI_OFF;
    char*     qlo   = smem + QLO_OFF;
    uint32_t* hist  = (uint32_t*)(smem + HIST_OFF);
    uint32_t* sidxA = (uint32_t*)(smem + SIDX_OFF);
    uint32_t* eidxA = (uint32_t*)(smem + EIDX_OFF);
    const uint32_t smem_u32 = sptr(smem);

    const int bh = blockIdx.x >> 7;
    const int qt = blockIdx.x & 127;
    const int q0 = qt * QT;
    const float* Qb = Qg + (size_t)bh * LL * DD;
    const float* Vb = Vg + (size_t)bh * LL * DD;

    const int tid  = threadIdx.x;
    const int lane = tid & 31;
    const int warp = tid >> 5;
    const unsigned FULL = 0xFFFFFFFFu;

    // ---- per-warp self-feeding K loads: warp w loads exactly the 8 rows
    //      (hi+lo) it will consume -> no block barrier in the mainloop ----
    const char* khiG = (const char*)KhiG + ((size_t)bh * LL) * 128;
    const char* kloG = (const char*)KloG + ((size_t)bh * LL) * 128;
    // lane -> (hi/lo, row, 64B-half): 8 rows x 2 halves x {hi,lo} = 32 units
    const int  u_r    = (lane & 15) >> 1;            // row 0..7 within warp slice
    const int  u_row  = warp * 8 + u_r;              // row within chunk
    const uint32_t u_colb = (uint32_t)(lane & 1) * 64;
    const char* u_gbase = ((lane < 16) ? khiG : kloG) + (size_t)u_row * 128 + u_colb;
    const uint32_t u_dhalf = (lane < 16) ? 0u : 16384u;
    uint32_t u_doff[4];
#pragma unroll
    for (int i = 0; i < 4; i++)
        u_doff[i] = u_dhalf + swz((uint32_t)u_row * 128 + u_colb + i * 16);

    auto issue_warp = [&](int ch) {
        const uint32_t stage = smem_u32 + KBUF_OFF + (ch & 1) * KSTAGE;
        const char* gsrc = u_gbase + (size_t)ch * KC * 128;
#pragma unroll
        for (int i = 0; i < 4; i++)
            cp_async16(stage + u_doff[i], gsrc + i * 16);
        asm volatile("cp.async.commit_group;" ::: "memory");
    };

    issue_warp(0);   // start own DMA before anything else

    // ---- load Q tile, split bf16 hi/lo into swizzled smem ----
    {
        int qrow = tid >> 5;
        int dc = (tid & 31) * 2;
        float2 qv = *(const float2*)(Qb + (size_t)(q0 + qrow) * DD + dc);
        __nv_bfloat162 hp = __floats2bfloat162_rn(qv.x, qv.y);
        float lx = qv.x - __bfloat162float(hp.x);
        float ly = qv.y - __bfloat162float(hp.y);
        uint32_t off = swz((uint32_t)(qrow * 128 + dc * 2));
        *(uint32_t*)(qhi + off) = *reinterpret_cast<uint32_t*>(&hp);
        *(uint32_t*)(qlo + off) = pack_bf16(lx, ly);
    }
    __syncthreads();   // Q visible to all warps

    // ---- preload A fragments (Q, m16k16 per k-step) into registers ----
    uint32_t Ah[4][4], Al[4][4];
    {
        int arow = lane & 15;                  // query row
        int acb = ((lane >> 4) & 1) * 16;      // k-halves
#pragma unroll
        for (int ks = 0; ks < 4; ks++) {
            uint32_t off = swz((uint32_t)(arow * 128 + ks * 32 + acb));
            ldsm_x4(Ah[ks], sptr(qhi + off));
            ldsm_x4(Al[ks], sptr(qlo + off));
        }
    }

    // B (K) addressing: warp owns keys [warp*8, warp*8+8) of each chunk.
    const uint32_t brow_off = (uint32_t)((warp * 8 + (lane & 7)) * 128 +
                                         ((lane >> 3) & 3) * 16);
    const uint32_t b0 = swz(brow_off);          // k-steps 0,1
    const uint32_t b1 = swz(brow_off + 64);     // k-steps 2,3

    // ---- mainloop: free-running warps, per-warp cp.async pipeline ----
#pragma unroll 2
    for (int ch = 0; ch < NCHUNK; ch++) {
        asm volatile("cp.async.wait_group 0;" ::: "memory");
        __syncwarp();                            // all lanes' copies landed
        if (ch + 1 < NCHUNK) issue_warp(ch + 1); // prefetch next chunk

        const uint32_t khi = smem_u32 + KBUF_OFF + (ch & 1) * KSTAGE;
        const uint32_t klo = khi + 16384;

        uint32_t Bh0[4], Bh1[4], Bl0[4], Bl1[4];
        ldsm_x4(Bh0, khi + b0);
        ldsm_x4(Bh1, khi + b1);
        ldsm_x4(Bl0, klo + b0);
        ldsm_x4(Bl1, klo + b1);

        // 3 independent accumulator chains (depth 4 each) for tensor-pipe ILP
        float ahh[4] = {0.f, 0.f, 0.f, 0.f};
        float alh[4] = {0.f, 0.f, 0.f, 0.f};
        float ahl[4] = {0.f, 0.f, 0.f, 0.f};
        mma16816(ahh, Ah[0], Bh0);      mma16816(alh, Al[0], Bh0);
        mma16816(ahl, Ah[0], Bl0);
        mma16816(ahh, Ah[1], Bh0 + 2);  mma16816(alh, Al[1], Bh0 + 2);
        mma16816(ahl, Ah[1], Bl0 + 2);
        mma16816(ahh, Ah[2], Bh1);      mma16816(alh, Al[2], Bh1);
        mma16816(ahl, Ah[2], Bl1);
        mma16816(ahh, Ah[3], Bh1 + 2);  mma16816(alh, Al[3], Bh1 + 2);
        mma16816(ahl, Ah[3], Bl1 + 2);

        // store 16q x 8k accumulator tile (rows = queries, cols = keys)
        {
            int qrow = lane >> 2;
            int kcol = ch * KC + warp * 8 + 2 * (lane & 3);
            float c0 = ahh[0] + alh[0] + ahl[0];
            float c1 = ahh[1] + alh[1] + ahl[1];
            float c2 = ahh[2] + alh[2] + ahl[2];
            float c3 = ahh[3] + alh[3] + ahl[3];
            *(float2*)&sc[qrow * SCORE_STRIDE + kcol]       = make_float2(c0, c1);
            *(float2*)&sc[(qrow + 8) * SCORE_STRIDE + kcol] = make_float2(c2, c3);
        }
    }
    __syncthreads();   // all scores visible before selection

    // ---- per-warp top-64 select on 16-bit ordered keys (one warp = one query) ----
    const float* row = sc + warp * SCORE_STRIDE;
    uint32_t* myhist = hist + warp * 256;
    uint32_t* sidx = sidxA + warp * 64;
    uint32_t* eidx = eidxA + warp * 64;

    for (int b = lane; b < 256; b += 32) myhist[b] = 0;
    __syncwarp();

    // pack keys into registers + fused round-1 histogram (digit = key>>8)
    uint32_t kp[32];
#pragma unroll
    for (int j = 0; j < 64; j += 2) {
        unsigned u0 = ordkey(row[j * 32 + lane]);
        unsigned u1 = ordkey(row[(j + 1) * 32 + lane]);
        kp[j >> 1] = (u0 >> 16) | (u1 & 0xFFFF0000u);
        atomicAdd(&myhist[u0 >> 24], 1u);
        atomicAdd(&myhist[u1 >> 24], 1u);
    }
    __syncwarp();

    int b1d, r1;
    hist_scan(myhist, lane, TOPK, b1d, r1);
    __syncwarp();

    for (int b = lane; b < 256; b += 32) myhist[b] = 0;
    __syncwarp();
#pragma unroll
    for (int j = 0; j < 64; j++) {
        unsigned k = (j & 1) ? (kp[j >> 1] >> 16) : (kp[j >> 1] & 0xFFFFu);
        if ((int)(k >> 8) == b1d) atomicAdd(&myhist[k & 255u], 1u);
    }
    __syncwarp();

    int b0sel, r2;
    hist_scan(myhist, lane, r1, b0sel, r2);
    const unsigned T16 = ((unsigned)b1d << 8) | (unsigned)b0sel;

    // collect: all keys > T16, then first r2 keys == T16 in index order
    {
        int cnt = 0, ecnt = 0;
        unsigned lt = (1u << lane) - 1u;
#pragma unroll
        for (int j = 0; j < 64; j++) {
            unsigned k = (j & 1) ? (kp[j >> 1] >> 16) : (kp[j >> 1] & 0xFFFFu);
            int i = j * 32 + lane;
            bool gt = (k > T16), eq = (k == T16);
            unsigned mg = __ballot_sync(FULL, gt);
            unsigned me = __ballot_sync(FULL, eq);
            if (gt) sidx[cnt + __popc(mg & lt)] = (uint32_t)i;
            if (eq) {
                int p = ecnt + __popc(me & lt);
                if (p < TOPK) eidx[p] = (uint32_t)i;
            }
            cnt += __popc(mg); ecnt += __popc(me);
        }
        __syncwarp();
        for (int j = lane; j < r2; j += 32) sidx[cnt + j] = eidx[j];
        __syncwarp();
    }

    // ---- softmax over selected (exact fp32) + V gather epilogue ----
    {
        int k0 = (int)sidx[lane], k1 = (int)sidx[lane + 32];
        float v0 = row[k0], v1 = row[k1];
        float m = fmaxf(v0, v1);
#pragma unroll
        for (int o = 16; o; o >>= 1) m = fmaxf(m, __shfl_xor_sync(FULL, m, o));
        float e0 = __expf(v0 - m), e1 = __expf(v1 - m);
        float s = e0 + e1;
#pragma unroll
        for (int o = 16; o; o >>= 1) s += __shfl_xor_sync(FULL, s, o);
        float inv = 1.f / s;
        float w0 = e0 * inv, w1 = e1 * inv;

        // lane covers output cols [2*lane, 2*lane+1] via float2 loads
        float o0 = 0.f, o1 = 0.f;
#pragma unroll 8
        for (int i = 0; i < 32; i++) {
            float wa = __shfl_sync(FULL, w0, i); int ka = __shfl_sync(FULL, k0, i);
            float wb = __shfl_sync(FULL, w1, i); int kb2 = __shfl_sync(FULL, k1, i);
            float2 va = *(const float2*)(Vb + (size_t)ka * DD + 2 * lane);
            float2 vb = *(const float2*)(Vb + (size_t)kb2 * DD + 2 * lane);
            o0 += wa * va.x + wb * vb.x;
            o1 += wa * va.y + wb * vb.y;
        }
        size_t ob = ((size_t)bh * LL + q0 + warp) * DD;
        *(float2*)(Og + ob + 2 * lane) = make_float2(o0, o1);
    }
}

extern "C" void kernel_launch(void* const* d_in, const int* in_sizes, int n_in,
                              void* d_out, int out_size)
{
    (void)in_sizes; (void)n_in; (void)out_size;
    const float* Q = (const float*)d_in[0];
    const float* K = (const float*)d_in[1];
    const float* V = (const float*)d_in[2];
    float* O = (float*)d_out;

    prep_k_kernel<<<PREP_N / 256, 256>>>((const float4*)K);

    cudaFuncSetAttribute(topk_attn_kernel,
                         cudaFuncAttributeMaxDynamicSharedMemorySize, SMEM_BYTES);
    dim3 grid(BB * HH * (LL / QT));   // 4096 CTAs
    topk_attn_kernel<<<grid, NTHREADS, SMEM_BYTES>>>(Q, V, O);
}

// round 10
// speedup vs baseline: 1.0044x; 1.0044x over previous
#include <cuda_runtime.h>
#include <cuda_bf16.h>
#include <cstdint>

#define BB 2
#define HH 16
#define LL 2048
#define DD 64
#define TOPK 64
#define QT 16           // queries per CTA
#define KC 128          // keys per chunk
#define NCHUNK (LL/KC)  // 16
#define NWARP 16
#define NTHREADS 512
#define SCORE_STRIDE 2052   // padded fp32 stride

// ---- smem layout (bytes) ----
#define SC_BYTES   (QT*SCORE_STRIDE*4)        // 131328
#define KBUF_OFF   SC_BYTES                   // 2 stages x 16KB (hi only)
#define KSTAGE     16384
#define QHI_OFF    (KBUF_OFF + 2*KSTAGE)      // 164096
#define QF32_OFF   (QHI_OFF + QT*128)         // 166144 (16 x 64 fp32)
#define HIST_OFF   (QF32_OFF + QT*256)        // 170240
#define SIDX_OFF   (HIST_OFF + NWARP*256*4)   // 186624
#define SVAL_OFF   (SIDX_OFF + NWARP*64*4)    // 190720 (doubles as eidx scratch)
#define SMEM_BYTES (SVAL_OFF + NWARP*64*4)    // 194816

// ---- persistent bf16 hi split of K (prep kernel output) ----
#define PREP_N (BB*HH*LL*DD/4)   // 1,048,576 float4 groups
__device__ __align__(16) uint2 KhiG[PREP_N];   // 8MB

__device__ __forceinline__ uint32_t swz(uint32_t o) { return o ^ ((o >> 3) & 0x70u); }
__device__ __forceinline__ uint32_t sptr(const void* p) {
    return (uint32_t)__cvta_generic_to_shared(p);
}
__device__ __forceinline__ void cp_async16(uint32_t dst, const void* src) {
    asm volatile("cp.async.cg.shared.global [%0], [%1], 16;" :: "r"(dst), "l"(src));
}
__device__ __forceinline__ void ldsm_x4(uint32_t a[4], uint32_t addr) {
    asm volatile("ldmatrix.sync.aligned.m8n8.x4.shared.b16 {%0,%1,%2,%3}, [%4];"
                 : "=r"(a[0]), "=r"(a[1]), "=r"(a[2]), "=r"(a[3]) : "r"(addr));
}
__device__ __forceinline__ void mma16816(float c[4], const uint32_t a[4], const uint32_t b[2]) {
    asm volatile("mma.sync.aligned.m16n8k16.row.col.f32.bf16.bf16.f32 "
                 "{%0,%1,%2,%3}, {%4,%5,%6,%7}, {%8,%9}, {%0,%1,%2,%3};"
                 : "+f"(c[0]), "+f"(c[1]), "+f"(c[2]), "+f"(c[3])
                 : "r"(a[0]), "r"(a[1]), "r"(a[2]), "r"(a[3]), "r"(b[0]), "r"(b[1]));
}
// sign-flip trick: monotonic unsigned ordering of floats
__device__ __forceinline__ unsigned ordkey(float f) {
    unsigned u = __float_as_uint(f);
    return (u & 0x80000000u) ? ~u : (u | 0x80000000u);
}

// ---- prep: K -> bf16 hi, row-major 128B rows ----
__global__ __launch_bounds__(256) void prep_k_kernel(const float4* __restrict__ K) {
    int i = blockIdx.x * 256 + threadIdx.x;
    float4 v = K[i];
    __nv_bfloat162 h01 = __floats2bfloat162_rn(v.x, v.y);
    __nv_bfloat162 h23 = __floats2bfloat162_rn(v.z, v.w);
    KhiG[i] = make_uint2(*reinterpret_cast<uint32_t*>(&h01),
                         *reinterpret_cast<uint32_t*>(&h23));
}

// warp-level scan over a 256-bin histogram: find digit bucket crossing rank r
__device__ __forceinline__ void hist_scan(const uint32_t* myhist, int lane, int r,
                                          int& bsel, int& rnew) {
    const unsigned FULL = 0xFFFFFFFFu;
    unsigned h[8], s = 0;
    int b0 = lane * 8;
#pragma unroll
    for (int j = 0; j < 8; j++) { h[j] = myhist[b0 + j]; s += h[j]; }
    unsigned t = s;                 // suffix-inclusive scan (high lanes = high digits)
#pragma unroll
    for (int d = 1; d < 32; d <<= 1) {
        unsigned v = __shfl_down_sync(FULL, t, d);
        if (lane + d < 32) t += v;
    }
    unsigned above = t - s;
    bool cross = (above < (unsigned)r) && ((unsigned)r <= t);
    unsigned cmask = __ballot_sync(FULL, cross);
    int src = __ffs(cmask) - 1;
    int bs = 0, rn = 0;
    if (cross) {
        unsigned cum = above;
#pragma unroll
        for (int j = 7; j >= 0; j--) {
            cum += h[j];
            if (cum >= (unsigned)r) { bs = b0 + j; rn = r - (int)(cum - h[j]); break; }
        }
    }
    bsel = __shfl_sync(FULL, bs, src);
    rnew = __shfl_sync(FULL, rn, src);
}

__global__ __launch_bounds__(NTHREADS, 1)
void topk_attn_kernel(const float* __restrict__ Qg, const float* __restrict__ Kg,
                      const float* __restrict__ Vg, float* __restrict__ Og)
{
    extern __shared__ char smem[];
    float*    sc    = (float*)smem;
    char*     qhi   = smem + QHI_OFF;
    float*    qf32  = (float*)(smem + QF32_OFF);
    uint32_t* hist  = (uint32_t*)(smem + HIST_OFF);
    uint32_t* sidxA = (uint32_t*)(smem + SIDX_OFF);
    uint32_t* svalA = (uint32_t*)(smem + SVAL_OFF);   // eidx scratch, then fp32 vals
    const uint32_t smem_u32 = sptr(smem);

    const int bh = blockIdx.x >> 7;
    const int qt = blockIdx.x & 127;
    const int q0 = qt * QT;
    const float* Qb = Qg + (size_t)bh * LL * DD;
    const float* Kb = Kg + (size_t)bh * LL * DD;
    const float* Vb = Vg + (size_t)bh * LL * DD;

    const int tid  = threadIdx.x;
    const int lane = tid & 31;
    const int warp = tid >> 5;
    const unsigned FULL = 0xFFFFFFFFu;

    // ---- block-wide K-hi chunk load via cp.async (16KB/chunk) ----
    const char* khiG = (const char*)KhiG + ((size_t)bh * LL) * 128;
    auto issue_chunk = [&](int ch) {
        const uint32_t dbase = smem_u32 + KBUF_OFF + (ch & 1) * KSTAGE;
        const size_t gbase = (size_t)ch * KC * 128;
#pragma unroll
        for (int it = 0; it < 2; it++) {
            uint32_t off = (uint32_t)(tid + it * NTHREADS) * 16;   // 0..16KB
            cp_async16(dbase + swz(off), khiG + gbase + off);
        }
        asm volatile("cp.async.commit_group;" ::: "memory");
    };

    issue_chunk(0);   // start DMA before anything else

    // ---- load Q tile: bf16 hi into swizzled smem + fp32 copy for rescore ----
    {
        int qrow = tid >> 5;
        int dc = (tid & 31) * 2;
        float2 qv = *(const float2*)(Qb + (size_t)(q0 + qrow) * DD + dc);
        __nv_bfloat162 hp = __floats2bfloat162_rn(qv.x, qv.y);
        uint32_t off = swz((uint32_t)(qrow * 128 + dc * 2));
        *(uint32_t*)(qhi + off) = *reinterpret_cast<uint32_t*>(&hp);
        *(float2*)(qf32 + qrow * 64 + dc) = qv;
    }
    __syncthreads();

    // ---- preload A fragments (Q-hi, m16k16 per k-step) ----
    uint32_t Ah[4][4];
    {
        int arow = lane & 15;
        int acb = ((lane >> 4) & 1) * 16;
#pragma unroll
        for (int ks = 0; ks < 4; ks++) {
            uint32_t off = swz((uint32_t)(arow * 128 + ks * 32 + acb));
            ldsm_x4(Ah[ks], sptr(qhi + off));
        }
    }

    // B (K) addressing: warp owns keys [warp*8, warp*8+8) of each chunk.
    const uint32_t brow_off = (uint32_t)((warp * 8 + (lane & 7)) * 128 +
                                         ((lane >> 3) & 3) * 16);
    const uint32_t b0 = swz(brow_off);          // k-steps 0,1
    const uint32_t b1 = swz(brow_off + 64);     // k-steps 2,3

    // ---- main loop: hi-only 1-pass MMA -> approx fp32 scores ----
    for (int ch = 0; ch < NCHUNK; ch++) {
        asm volatile("cp.async.wait_group 0;" ::: "memory");
        __syncthreads();
        if (ch + 1 < NCHUNK) issue_chunk(ch + 1);

        const uint32_t khi = smem_u32 + KBUF_OFF + (ch & 1) * KSTAGE;
        uint32_t Bh0[4], Bh1[4];
        ldsm_x4(Bh0, khi + b0);
        ldsm_x4(Bh1, khi + b1);

        float acc[4] = {0.f, 0.f, 0.f, 0.f};
        mma16816(acc, Ah[0], Bh0);
        mma16816(acc, Ah[1], Bh0 + 2);
        mma16816(acc, Ah[2], Bh1);
        mma16816(acc, Ah[3], Bh1 + 2);

        {
            int qrow = lane >> 2;
            int kcol = ch * KC + warp * 8 + 2 * (lane & 3);
            *(float2*)&sc[qrow * SCORE_STRIDE + kcol]       = make_float2(acc[0], acc[1]);
            *(float2*)&sc[(qrow + 8) * SCORE_STRIDE + kcol] = make_float2(acc[2], acc[3]);
        }
    }
    __syncthreads();

    // ---- per-warp top-64 select on 16-bit keys of approx scores ----
    const float* row = sc + warp * SCORE_STRIDE;
    uint32_t* myhist = hist + warp * 256;
    uint32_t* sidx = sidxA + warp * 64;
    uint32_t* eidx = svalA + warp * 64;   // scratch during collect

    for (int b = lane; b < 256; b += 32) myhist[b] = 0;
    __syncwarp();

    uint32_t kp[32];
#pragma unroll
    for (int j = 0; j < 64; j += 2) {
        unsigned u0 = ordkey(row[j * 32 + lane]);
        unsigned u1 = ordkey(row[(j + 1) * 32 + lane]);
        kp[j >> 1] = (u0 >> 16) | (u1 & 0xFFFF0000u);
        atomicAdd(&myhist[u0 >> 24], 1u);
        atomicAdd(&myhist[u1 >> 24], 1u);
    }
    __syncwarp();

    int b1d, r1;
    hist_scan(myhist, lane, TOPK, b1d, r1);
    __syncwarp();

    for (int b = lane; b < 256; b += 32) myhist[b] = 0;
    __syncwarp();
#pragma unroll
    for (int j = 0; j < 64; j++) {
        unsigned k = (j & 1) ? (kp[j >> 1] >> 16) : (kp[j >> 1] & 0xFFFFu);
        if ((int)(k >> 8) == b1d) atomicAdd(&myhist[k & 255u], 1u);
    }
    __syncwarp();

    int b0sel, r2;
    hist_scan(myhist, lane, r1, b0sel, r2);
    const unsigned T16 = ((unsigned)b1d << 8) | (unsigned)b0sel;

    // collect: all keys > T16, then first r2 keys == T16 in index order
    {
        int cnt = 0, ecnt = 0;
        unsigned lt = (1u << lane) - 1u;
#pragma unroll
        for (int j = 0; j < 64; j++) {
            unsigned k = (j & 1) ? (kp[j >> 1] >> 16) : (kp[j >> 1] & 0xFFFFu);
            int i = j * 32 + lane;
            bool gt = (k > T16), eq = (k == T16);
            unsigned mg = __ballot_sync(FULL, gt);
            unsigned me = __ballot_sync(FULL, eq);
            if (gt) sidx[cnt + __popc(mg & lt)] = (uint32_t)i;
            if (eq) {
                int p = ecnt + __popc(me & lt);
                if (p < TOPK) eidx[p] = (uint32_t)i;
            }
            cnt += __popc(mg); ecnt += __popc(me);
        }
        __syncwarp();
        for (int j = lane; j < r2; j += 32) sidx[cnt + j] = eidx[j];
        __syncwarp();
    }

    // ---- exact fp32 rescore of the 64 selected keys ----
    // 4-lane groups: group g (lanes 4g..4g+3) handles key sidx[8p+g], each lane
    // covers 16 dims; 8 passes cover 64 keys.
    float* svalf = (float*)(svalA + warp * 64);   // overwrite eidx scratch
    {
        const int sub = lane & 3, grp = lane >> 2;
        const float* qf = qf32 + warp * 64 + sub * 16;
        float4 qr0 = *(const float4*)(qf);
        float4 qr1 = *(const float4*)(qf + 4);
        float4 qr2 = *(const float4*)(qf + 8);
        float4 qr3 = *(const float4*)(qf + 12);
#pragma unroll
        for (int p = 0; p < 8; p++) {
            int key = (int)sidx[p * 8 + grp];
            const float* kr = Kb + (size_t)key * DD + sub * 16;
            float4 k0v = *(const float4*)(kr);
            float4 k1v = *(const float4*)(kr + 4);
            float4 k2v = *(const float4*)(kr + 8);
            float4 k3v = *(const float4*)(kr + 12);
            float d = qr0.x * k0v.x + qr0.y * k0v.y + qr0.z * k0v.z + qr0.w * k0v.w;
            d += qr1.x * k1v.x + qr1.y * k1v.y + qr1.z * k1v.z + qr1.w * k1v.w;
            d += qr2.x * k2v.x + qr2.y * k2v.y + qr2.z * k2v.z + qr2.w * k2v.w;
            d += qr3.x * k3v.x + qr3.y * k3v.y + qr3.z * k3v.z + qr3.w * k3v.w;
            d += __shfl_xor_sync(FULL, d, 1);
            d += __shfl_xor_sync(FULL, d, 2);
            if (sub == 0) svalf[p * 8 + grp] = d;
        }
        __syncwarp();
    }

    // ---- softmax over exact values + V gather epilogue ----
    {
        int k0 = (int)sidx[lane], k1 = (int)sidx[lane + 32];
        float v0 = svalf[lane], v1 = svalf[lane + 32];
        float m = fmaxf(v0, v1);
#pragma unroll
        for (int o = 16; o; o >>= 1) m = fmaxf(m, __shfl_xor_sync(FULL, m, o));
        float e0 = __expf(v0 - m), e1 = __expf(v1 - m);
        float s = e0 + e1;
#pragma unroll
        for (int o = 16; o; o >>= 1) s += __shfl_xor_sync(FULL, s, o);
        float inv = 1.f / s;
        float w0 = e0 * inv, w1 = e1 * inv;

        float o0 = 0.f, o1 = 0.f;
#pragma unroll 8
        for (int i = 0; i < 32; i++) {
            float wa = __shfl_sync(FULL, w0, i); int ka = __shfl_sync(FULL, k0, i);
            float wb = __shfl_sync(FULL, w1, i); int kb2 = __shfl_sync(FULL, k1, i);
            float2 va = *(const float2*)(Vb + (size_t)ka * DD + 2 * lane);
            float2 vb = *(const float2*)(Vb + (size_t)kb2 * DD + 2 * lane);
            o0 += wa * va.x + wb * vb.x;
            o1 += wa * va.y + wb * vb.y;
        }
        size_t ob = ((size_t)bh * LL + q0 + warp) * DD;
        *(float2*)(Og + ob + 2 * lane) = make_float2(o0, o1);
    }
}

extern "C" void kernel_launch(void* const* d_in, const int* in_sizes, int n_in,
                              void* d_out, int out_size)
{
    (void)in_sizes; (void)n_in; (void)out_size;
    const float* Q = (const float*)d_in[0];
    const float* K = (const float*)d_in[1];
    const float* V = (const float*)d_in[2];
    float* O = (float*)d_out;

    prep_k_kernel<<<PREP_N / 256, 256>>>((const float4*)K);

    cudaFuncSetAttribute(topk_attn_kernel,
                         cudaFuncAttributeMaxDynamicSharedMemorySize, SMEM_BYTES);
    dim3 grid(BB * HH * (LL / QT));   // 4096 CTAs
    topk_attn_kernel<<<grid, NTHREADS, SMEM_BYTES>>>(Q, K, V, O);
}

// round 11
// speedup vs baseline: 1.1190x; 1.1141x over previous
#include <cuda_runtime.h>
#include <cuda_bf16.h>
#include <cstdint>

#define BB 2
#define HH 16
#define LL 2048
#define DD 64
#define TOPK 64
#define QT 16           // queries per CTA
#define KC 128          // keys per chunk
#define NCHUNK (LL/KC)  // 16
#define NWARP 8
#define NTHREADS 256
#define SS 2056         // score stride in u16 (pad vs 2048 for STS banks)

// ---- smem layout (bytes) ----
#define SC_BYTES   (QT*SS*2)              // 65792  (16-bit ordkeys)
#define KBUF_OFF   SC_BYTES               // 2 stages x 16KB (K-hi)
#define KSTAGE     16384
#define QHI_OFF    (KBUF_OFF + 2*KSTAGE)  // 98560
#define SMEM_BYTES (QHI_OFF + 2048)       // 100608 -> 2 CTAs/SM
// overlays inside the (dead after mainloop) K buffer:
#define HIST_OFF   KBUF_OFF               // 8 warps * 1KB = 8KB
#define SIDX_OFF   (KBUF_OFF + 8192)      // 16q * 64 * 4 = 4KB
#define EIDX_OFF   (KBUF_OFF + 12288)     // 4KB
#define SVAL_OFF   (KBUF_OFF + 16384)     // 4KB

// ---- persistent bf16-hi split of K (prep kernel output) ----
#define PREP_N (BB*HH*LL*DD/4)
__device__ __align__(16) uint2 KhiG[PREP_N];   // 8MB

__device__ __forceinline__ uint32_t swz(uint32_t o) { return o ^ ((o >> 3) & 0x70u); }
__device__ __forceinline__ uint32_t sptr(const void* p) {
    return (uint32_t)__cvta_generic_to_shared(p);
}
__device__ __forceinline__ void cp_async16(uint32_t dst, const void* src) {
    asm volatile("cp.async.cg.shared.global [%0], [%1], 16;" :: "r"(dst), "l"(src));
}
__device__ __forceinline__ void ldsm_x4(uint32_t a[4], uint32_t addr) {
    asm volatile("ldmatrix.sync.aligned.m8n8.x4.shared.b16 {%0,%1,%2,%3}, [%4];"
                 : "=r"(a[0]), "=r"(a[1]), "=r"(a[2]), "=r"(a[3]) : "r"(addr));
}
__device__ __forceinline__ void ldsm_x2(uint32_t b[2], uint32_t addr) {
    asm volatile("ldmatrix.sync.aligned.m8n8.x2.shared.b16 {%0,%1}, [%2];"
                 : "=r"(b[0]), "=r"(b[1]) : "r"(addr));
}
__device__ __forceinline__ void mma16816(float c[4], const uint32_t a[4], const uint32_t b[2]) {
    asm volatile("mma.sync.aligned.m16n8k16.row.col.f32.bf16.bf16.f32 "
                 "{%0,%1,%2,%3}, {%4,%5,%6,%7}, {%8,%9}, {%0,%1,%2,%3};"
                 : "+f"(c[0]), "+f"(c[1]), "+f"(c[2]), "+f"(c[3])
                 : "r"(a[0]), "r"(a[1]), "r"(a[2]), "r"(a[3]), "r"(b[0]), "r"(b[1]));
}
// 16-bit monotone ordering key of a float
__device__ __forceinline__ unsigned ord16(float f) {
    unsigned u = __float_as_uint(f);
    u = (u & 0x80000000u) ? ~u : (u | 0x80000000u);
    return u >> 16;
}

// ---- prep: K -> bf16 hi, row-major 128B rows ----
__global__ __launch_bounds__(256) void prep_k_kernel(const float4* __restrict__ K) {
    int i = blockIdx.x * 256 + threadIdx.x;
    float4 v = K[i];
    __nv_bfloat162 h01 = __floats2bfloat162_rn(v.x, v.y);
    __nv_bfloat162 h23 = __floats2bfloat162_rn(v.z, v.w);
    KhiG[i] = make_uint2(*reinterpret_cast<uint32_t*>(&h01),
                         *reinterpret_cast<uint32_t*>(&h23));
}

// warp-level scan over a 256-bin histogram: find digit bucket crossing rank r
__device__ __forceinline__ void hist_scan(const uint32_t* myhist, int lane, int r,
                                          int& bsel, int& rnew) {
    const unsigned FULL = 0xFFFFFFFFu;
    unsigned h[8], s = 0;
    int b0 = lane * 8;
#pragma unroll
    for (int j = 0; j < 8; j++) { h[j] = myhist[b0 + j]; s += h[j]; }
    unsigned t = s;
#pragma unroll
    for (int d = 1; d < 32; d <<= 1) {
        unsigned v = __shfl_down_sync(FULL, t, d);
        if (lane + d < 32) t += v;
    }
    unsigned above = t - s;
    bool cross = (above < (unsigned)r) && ((unsigned)r <= t);
    unsigned cmask = __ballot_sync(FULL, cross);
    int src = __ffs(cmask) - 1;
    int bs = 0, rn = 0;
    if (cross) {
        unsigned cum = above;
#pragma unroll
        for (int j = 7; j >= 0; j--) {
            cum += h[j];
            if (cum >= (unsigned)r) { bs = b0 + j; rn = r - (int)(cum - h[j]); break; }
        }
    }
    bsel = __shfl_sync(FULL, bs, src);
    rnew = __shfl_sync(FULL, rn, src);
}

__global__ __launch_bounds__(NTHREADS, 2)
void topk_attn_kernel(const float* __restrict__ Qg, const float* __restrict__ Kg,
                      const float* __restrict__ Vg, float* __restrict__ Og)
{
    extern __shared__ char smem[];
    unsigned short* sc16 = (unsigned short*)smem;
    char*     qhi   = smem + QHI_OFF;
    uint32_t* hist  = (uint32_t*)(smem + HIST_OFF);
    int*      sidxA = (int*)(smem + SIDX_OFF);
    int*      eidxA = (int*)(smem + EIDX_OFF);
    float*    svalA = (float*)(smem + SVAL_OFF);
    const uint32_t smem_u32 = sptr(smem);

    const int bh = blockIdx.x >> 7;
    const int qt = blockIdx.x & 127;
    const int q0 = qt * QT;
    const float* Qb = Qg + (size_t)bh * LL * DD;
    const float* Kb = Kg + (size_t)bh * LL * DD;
    const float* Vb = Vg + (size_t)bh * LL * DD;

    const int tid  = threadIdx.x;
    const int lane = tid & 31;
    const int warp = tid >> 5;    // 0..7
    const unsigned FULL = 0xFFFFFFFFu;

    // ---- block-wide K-hi chunk load (16KB) via cp.async ----
    const char* khiG = (const char*)KhiG + ((size_t)bh * LL) * 128;
    auto issue_chunk = [&](int ch) {
        const uint32_t dbase = smem_u32 + KBUF_OFF + (ch & 1) * KSTAGE;
        const size_t gbase = (size_t)ch * KC * 128;
#pragma unroll
        for (int it = 0; it < 4; it++) {
            uint32_t off = (uint32_t)(tid + it * NTHREADS) * 16;   // 0..16KB
            cp_async16(dbase + swz(off), khiG + gbase + off);
        }
        asm volatile("cp.async.commit_group;" ::: "memory");
    };

    issue_chunk(0);

    // ---- load Q tile (16 x 64 fp32 -> bf16 hi, swizzled) ----
    {
        int qrow = tid >> 4;          // 0..15
        int dc = (tid & 15) * 4;      // 0..60
        float4 qv4 = *(const float4*)(Qb + (size_t)(q0 + qrow) * DD + dc);
        __nv_bfloat162 h01 = __floats2bfloat162_rn(qv4.x, qv4.y);
        __nv_bfloat162 h23 = __floats2bfloat162_rn(qv4.z, qv4.w);
        uint32_t off = swz((uint32_t)(qrow * 128 + dc * 2));
        *(uint2*)(qhi + off) = make_uint2(*reinterpret_cast<uint32_t*>(&h01),
                                          *reinterpret_cast<uint32_t*>(&h23));
    }
    __syncthreads();

    // ---- preload B fragments (Q-hi): 2 n-tiles x 4 k-steps ----
    uint32_t Bh[2][4][2];
#pragma unroll
    for (int nt = 0; nt < 2; nt++) {
        int qrow = nt * 8 + (lane & 7);
        int cb = ((lane >> 3) & 1) * 16;
#pragma unroll
        for (int ks = 0; ks < 4; ks++) {
            uint32_t off = swz((uint32_t)(qrow * 128 + ks * 32 + cb));
            ldsm_x2(Bh[nt][ks], sptr(qhi + off));
        }
    }
    // A (K-hi): warp owns 16 key rows [warp*16, warp*16+16) of each chunk
    uint32_t aoff[4];
#pragma unroll
    for (int ks = 0; ks < 4; ks++)
        aoff[ks] = swz((uint32_t)((warp * 16 + (lane & 15)) * 128 +
                                  ks * 32 + ((lane >> 4) & 1) * 16));

    // ---- main loop: hi-only MMA -> 16-bit ordkey scores in smem ----
    for (int ch = 0; ch < NCHUNK; ch++) {
        asm volatile("cp.async.wait_group 0;" ::: "memory");
        __syncthreads();
        if (ch + 1 < NCHUNK) issue_chunk(ch + 1);

        const uint32_t khi = smem_u32 + KBUF_OFF + (ch & 1) * KSTAGE;
        uint32_t A0[4], A1[4], A2[4], A3[4];
        ldsm_x4(A0, khi + aoff[0]);
        ldsm_x4(A1, khi + aoff[1]);
        ldsm_x4(A2, khi + aoff[2]);
        ldsm_x4(A3, khi + aoff[3]);

        float c0[4] = {0.f, 0.f, 0.f, 0.f};   // n-tile 0 (queries 0-7)
        float c1[4] = {0.f, 0.f, 0.f, 0.f};   // n-tile 1 (queries 8-15)
        mma16816(c0, A0, Bh[0][0]);  mma16816(c1, A0, Bh[1][0]);
        mma16816(c0, A1, Bh[0][1]);  mma16816(c1, A1, Bh[1][1]);
        mma16816(c0, A2, Bh[0][2]);  mma16816(c1, A2, Bh[1][2]);
        mma16816(c0, A3, Bh[0][3]);  mma16816(c1, A3, Bh[1][3]);

        // accumulator (16 keys x 8 queries): rows=keys, cols=queries (round-2 map)
        {
            int krow = ch * KC + warp * 16 + (lane >> 2);
            int qc = 2 * (lane & 3);
            sc16[ qc      * SS + krow    ] = (unsigned short)ord16(c0[0]);
            sc16[(qc + 1) * SS + krow    ] = (unsigned short)ord16(c0[1]);
            sc16[ qc      * SS + krow + 8] = (unsigned short)ord16(c0[2]);
            sc16[(qc + 1) * SS + krow + 8] = (unsigned short)ord16(c0[3]);
            sc16[(qc + 8) * SS + krow    ] = (unsigned short)ord16(c1[0]);
            sc16[(qc + 9) * SS + krow    ] = (unsigned short)ord16(c1[1]);
            sc16[(qc + 8) * SS + krow + 8] = (unsigned short)ord16(c1[2]);
            sc16[(qc + 9) * SS + krow + 8] = (unsigned short)ord16(c1[3]);
        }
    }
    __syncthreads();   // scores visible; K buffer dead -> overlays legal

    uint32_t* myhist = hist + warp * 256;

    // ---- per-warp: 2 queries (warp, warp+8), fully warp-local epilogue ----
#pragma unroll 1
    for (int qq = 0; qq < 2; qq++) {
        const int q = warp + qq * 8;
        const uint32_t* row32 = (const uint32_t*)(sc16 + (size_t)q * SS);
        int* sidx = sidxA + q * 64;
        int* eidx = eidxA + q * 64;
        float* svalf = svalA + q * 64;

        // load 64 packed ord16 keys/lane + round-1 histogram (top byte)
        for (int b = lane; b < 256; b += 32) myhist[b] = 0;
        __syncwarp();
        uint32_t kp[32];
#pragma unroll
        for (int j = 0; j < 32; j++) {
            uint32_t w2 = row32[j * 32 + lane];    // keys j*64+2*lane, +1
            kp[j] = w2;
            atomicAdd(&myhist[(w2 >> 8) & 255u], 1u);
            atomicAdd(&myhist[w2 >> 24], 1u);
        }
        __syncwarp();
        int b1d, r1;
        hist_scan(myhist, lane, TOPK, b1d, r1);
        __syncwarp();

        // round-2 histogram (low byte within bucket b1d)
        for (int b = lane; b < 256; b += 32) myhist[b] = 0;
        __syncwarp();
#pragma unroll
        for (int j = 0; j < 32; j++) {
            uint32_t w2 = kp[j];
            if ((int)((w2 >> 8) & 255u) == b1d) atomicAdd(&myhist[w2 & 255u], 1u);
            if ((int)(w2 >> 24) == b1d)         atomicAdd(&myhist[(w2 >> 16) & 255u], 1u);
        }
        __syncwarp();
        int b0sel, r2;
        hist_scan(myhist, lane, r1, b0sel, r2);
        const unsigned T16 = ((unsigned)b1d << 8) | (unsigned)b0sel;

        // collect: keys > T16 (any order-stable), then first r2 == T16
        {
            int cnt = 0, ecnt = 0;
            unsigned lt = (1u << lane) - 1u;
#pragma unroll
            for (int j = 0; j < 32; j++) {
                uint32_t w2 = kp[j];
                unsigned klo = w2 & 0xFFFFu, khi2 = w2 >> 16;
                int ilo = j * 64 + 2 * lane;
                // low halves
                bool gt = (klo > T16), eq = (klo == T16);
                unsigned mg = __ballot_sync(FULL, gt);
                unsigned me = __ballot_sync(FULL, eq);
                if (gt) sidx[cnt + __popc(mg & lt)] = ilo;
                if (eq) { int p = ecnt + __popc(me & lt); if (p < TOPK) eidx[p] = ilo; }
                cnt += __popc(mg); ecnt += __popc(me);
                // high halves
                gt = (khi2 > T16); eq = (khi2 == T16);
                mg = __ballot_sync(FULL, gt);
                me = __ballot_sync(FULL, eq);
                if (gt) sidx[cnt + __popc(mg & lt)] = ilo + 1;
                if (eq) { int p = ecnt + __popc(me & lt); if (p < TOPK) eidx[p] = ilo + 1; }
                cnt += __popc(mg); ecnt += __popc(me);
            }
            __syncwarp();
            for (int j = lane; j < r2; j += 32) sidx[cnt + j] = eidx[j];
            __syncwarp();
        }

        // ---- exact fp32 rescore: warp-per-key, coalesced (1 LDG.64 = full row) ----
        {
            float2 qv = *(const float2*)(Qb + (size_t)(q0 + q) * DD + 2 * lane);
#pragma unroll 1
            for (int p = 0; p < 64; p += 4) {
                int key0 = sidx[p],     key1 = sidx[p + 1];
                int key2 = sidx[p + 2], key3 = sidx[p + 3];
                float2 kv0 = *(const float2*)(Kb + (size_t)key0 * DD + 2 * lane);
                float2 kv1 = *(const float2*)(Kb + (size_t)key1 * DD + 2 * lane);
                float2 kv2 = *(const float2*)(Kb + (size_t)key2 * DD + 2 * lane);
                float2 kv3 = *(const float2*)(Kb + (size_t)key3 * DD + 2 * lane);
                float d0 = qv.x * kv0.x + qv.y * kv0.y;
                float d1 = qv.x * kv1.x + qv.y * kv1.y;
                float d2 = qv.x * kv2.x + qv.y * kv2.y;
                float d3 = qv.x * kv3.x + qv.y * kv3.y;
#pragma unroll
                for (int o = 16; o; o >>= 1) {
                    d0 += __shfl_xor_sync(FULL, d0, o);
                    d1 += __shfl_xor_sync(FULL, d1, o);
                    d2 += __shfl_xor_sync(FULL, d2, o);
                    d3 += __shfl_xor_sync(FULL, d3, o);
                }
                if (lane == 0) {
                    svalf[p] = d0; svalf[p + 1] = d1;
                    svalf[p + 2] = d2; svalf[p + 3] = d3;
                }
            }
            __syncwarp();
        }

        // ---- softmax (exact fp32) + V gather ----
        {
            int k0 = sidx[lane], k1 = sidx[lane + 32];
            float v0 = svalf[lane], v1 = svalf[lane + 32];
            float m = fmaxf(v0, v1);
#pragma unroll
            for (int o = 16; o; o >>= 1) m = fmaxf(m, __shfl_xor_sync(FULL, m, o));
            float e0 = __expf(v0 - m), e1 = __expf(v1 - m);
            float s = e0 + e1;
#pragma unroll
            for (int o = 16; o; o >>= 1) s += __shfl_xor_sync(FULL, s, o);
            float inv = 1.f / s;
            float w0 = e0 * inv, w1 = e1 * inv;

            float o0 = 0.f, o1 = 0.f;
#pragma unroll 8
            for (int i = 0; i < 32; i++) {
                float wa = __shfl_sync(FULL, w0, i); int ka = __shfl_sync(FULL, k0, i);
                float wb = __shfl_sync(FULL, w1, i); int kb2 = __shfl_sync(FULL, k1, i);
                float2 va = *(const float2*)(Vb + (size_t)ka * DD + 2 * lane);
                float2 vb = *(const float2*)(Vb + (size_t)kb2 * DD + 2 * lane);
                o0 += wa * va.x + wb * vb.x;
                o1 += wa * va.y + wb * vb.y;
            }
            size_t ob = ((size_t)bh * LL + q0 + q) * DD;
            *(float2*)(Og + ob + 2 * lane) = make_float2(o0, o1);
        }
    }
}

extern "C" void kernel_launch(void* const* d_in, const int* in_sizes, int n_in,
                              void* d_out, int out_size)
{
    (void)in_sizes; (void)n_in; (void)out_size;
    const float* Q = (const float*)d_in[0];
    const float* K = (const float*)d_in[1];
    const float* V = (const float*)d_in[2];
    float* O = (float*)d_out;

    prep_k_kernel<<<PREP_N / 256, 256>>>((const float4*)K);

    cudaFuncSetAttribute(topk_attn_kernel,
                         cudaFuncAttributeMaxDynamicSharedMemorySize, SMEM_BYTES);
    dim3 grid(BB * HH * (LL / QT));   // 4096 CTAs
    topk_attn_kernel<<<grid, NTHREADS, SMEM_BYTES>>>(Q, K, V, O);
}